// round 7
// baseline (speedup 1.0000x reference)
#include <cuda_runtime.h>
#include <cstdint>
#include <cstddef>

#define NN 100000
#define NE 1600000
#define D  128

// Scratch (static device globals; no allocation allowed)
__device__ int   g_is64;                  // 1 if edge_index is int64, else int32
__device__ int   g_src[NE];
__device__ int   g_dst[NE];
__device__ float g_dinv[NN];
__device__ float g_HS [(size_t)NN * D];   // dinv[u] * (x @ W1)[u]
__device__ float g_ACC[(size_t)NN * D];   // scatter accumulator, layer 1
__device__ float g_HS2[NN * 2];           // dinv[u] * (relu(...) @ W2)[u]
__device__ float g_ACC2[NN * 2];          // scatter accumulator, layer 2

// ---------------------------------------------------------------------------
// 0a) probe edge_index dtype: if int64, all odd 32-bit words are 0 (high words
//     of values < 2^31). If int32, odd words are random indices (~never all 0).
// ---------------------------------------------------------------------------
__global__ void probe_kernel(const int* __restrict__ raw) {
    __shared__ int nz;
    if (threadIdx.x == 0) nz = 0;
    __syncthreads();
    // sample 256 odd words spread across the buffer (safe under either dtype:
    // int32 buffer has 2*NE = 3.2M words; we touch < 2*NE)
    const int idx = 2 * (threadIdx.x * 4096) + 1;   // < 2*NE for tid<256
    if (raw[idx] != 0) atomicAdd(&nz, 1);
    __syncthreads();
    if (threadIdx.x == 0) g_is64 = (nz == 0) ? 1 : 0;
}

// 0b) normalize edges to int32 src/dst
__global__ void convert_kernel(const int* __restrict__ raw) {
    const int e = blockIdx.x * blockDim.x + threadIdx.x;
    if (e >= NE) return;
    if (g_is64) {
        g_src[e] = raw[2 * e];              // little-endian low word
        g_dst[e] = raw[2 * (NE + e)];
    } else {
        g_src[e] = raw[e];
        g_dst[e] = raw[NE + e];
    }
}

// ---------------------------------------------------------------------------
// 1) init: zero ACC, ACC2; deg=1 (self loop)
// ---------------------------------------------------------------------------
__global__ void init_kernel() {
    const int i = blockIdx.x * blockDim.x + threadIdx.x;   // float4 index
    const int ND4 = NN * D / 4;
    float4 z = make_float4(0.f, 0.f, 0.f, 0.f);
    if (i < ND4) ((float4*)g_ACC)[i] = z;
    if (i < NN * 2 / 4) ((float4*)g_ACC2)[i] = z;
    if (i < NN / 4) ((float4*)g_dinv)[i] = make_float4(1.f, 1.f, 1.f, 1.f);
}

// ---------------------------------------------------------------------------
// 2) degree accumulation on dst
// ---------------------------------------------------------------------------
__global__ void deg_kernel() {
    const int e = blockIdx.x * blockDim.x + threadIdx.x;
    if (e < NE) atomicAdd(&g_dinv[g_dst[e]], 1.0f);
}

// 3) dinv = rsqrt(deg)
__global__ void rsqrt_kernel() {
    const int i = blockIdx.x * blockDim.x + threadIdx.x;
    if (i < NN) g_dinv[i] = rsqrtf(g_dinv[i]);
}

// ---------------------------------------------------------------------------
// 4) HS = dinv[:,None] * (X @ W1)   fp32 SGEMM, BM=128 BN=128 BK=16, 8x8/thr
// ---------------------------------------------------------------------------
__global__ __launch_bounds__(256) void gemm1_kernel(const float* __restrict__ X,
                                                    const float* __restrict__ W1) {
    __shared__ float As[16][132];   // [k][m], padded
    __shared__ float Bs[16][128];   // [k][n]
    const int tid = threadIdx.x;
    const int tx = tid & 15;
    const int ty = tid >> 4;
    const int m0 = blockIdx.x * 128;

    float acc[8][8];
#pragma unroll
    for (int i = 0; i < 8; i++)
#pragma unroll
        for (int j = 0; j < 8; j++) acc[i][j] = 0.f;

#pragma unroll 1
    for (int k0 = 0; k0 < 128; k0 += 16) {
        // X tile (128 rows x 16 cols), store transposed into As[k][m]
        {
            const int r = tid >> 2;          // 0..63
            const int c = (tid & 3) << 2;    // 0,4,8,12
#pragma unroll
            for (int rr = 0; rr < 128; rr += 64) {
                const int gr = m0 + r + rr;
                float4 v = make_float4(0.f, 0.f, 0.f, 0.f);
                if (gr < NN) v = *(const float4*)(X + (size_t)gr * 128 + k0 + c);
                As[c + 0][r + rr] = v.x;
                As[c + 1][r + rr] = v.y;
                As[c + 2][r + rr] = v.z;
                As[c + 3][r + rr] = v.w;
            }
        }
        // W1 tile (16 rows x 128 cols)
        {
            const int wr = tid >> 5;         // 0..7
            const int wc = (tid & 31) << 2;
#pragma unroll
            for (int kk = 0; kk < 16; kk += 8)
                *(float4*)&Bs[wr + kk][wc] =
                    *(const float4*)(W1 + (size_t)(k0 + wr + kk) * 128 + wc);
        }
        __syncthreads();
#pragma unroll
        for (int kk = 0; kk < 16; kk++) {
            float a[8], b[8];
            *(float4*)(a)     = *(const float4*)&As[kk][ty * 4];
            *(float4*)(a + 4) = *(const float4*)&As[kk][64 + ty * 4];
            *(float4*)(b)     = *(const float4*)&Bs[kk][tx * 4];
            *(float4*)(b + 4) = *(const float4*)&Bs[kk][64 + tx * 4];
#pragma unroll
            for (int i = 0; i < 8; i++)
#pragma unroll
                for (int j = 0; j < 8; j++)
                    acc[i][j] = fmaf(a[i], b[j], acc[i][j]);
        }
        __syncthreads();
    }
    // epilogue: scale by dinv, write HS
#pragma unroll
    for (int i = 0; i < 8; i++) {
        const int gr = m0 + ((i < 4) ? (ty * 4 + i) : (64 + ty * 4 + i - 4));
        if (gr >= NN) continue;
        const float s = g_dinv[gr];
        float4 v0, v1;
        v0.x = acc[i][0] * s; v0.y = acc[i][1] * s;
        v0.z = acc[i][2] * s; v0.w = acc[i][3] * s;
        v1.x = acc[i][4] * s; v1.y = acc[i][5] * s;
        v1.z = acc[i][6] * s; v1.w = acc[i][7] * s;
        *(float4*)(g_HS + (size_t)gr * 128 + tx * 4)      = v0;
        *(float4*)(g_HS + (size_t)gr * 128 + 64 + tx * 4) = v1;
    }
}

// ---------------------------------------------------------------------------
// 5) scatter layer 1: ACC[dst] += HS[src]   (one warp per edge, float4 reds)
// ---------------------------------------------------------------------------
__global__ __launch_bounds__(256) void scatter1_kernel() {
    const int w = (blockIdx.x * blockDim.x + threadIdx.x) >> 5;
    const int lane = threadIdx.x & 31;
    if (w >= NE) return;
    const int s = g_src[w];
    const int d = g_dst[w];
    float4 v = ((const float4*)(g_HS + (size_t)s * 128))[lane];
    atomicAdd(((float4*)(g_ACC + (size_t)d * 128)) + lane, v);
}

// ---------------------------------------------------------------------------
// 6) layer-1 epilogue fused with layer-2 linear:
//    x2 = relu(dinv*(ACC+HS) + b1);  HS2 = dinv * (x2 @ W2)   (warp per node)
// ---------------------------------------------------------------------------
__global__ __launch_bounds__(256) void layer2_kernel(const float* __restrict__ b1,
                                                     const float* __restrict__ W2) {
    __shared__ float sW2[256];
    __shared__ float sb1[128];
    const int tid = threadIdx.x;
    if (tid < 256) sW2[tid] = W2[tid];
    if (tid < 128) sb1[tid] = b1[tid];
    __syncthreads();
    const int v = (blockIdx.x * blockDim.x + tid) >> 5;
    const int lane = tid & 31;
    if (v >= NN) return;
    const float dinv = g_dinv[v];
    const float4 a = ((const float4*)(g_ACC + (size_t)v * 128))[lane];
    const float4 h = ((const float4*)(g_HS  + (size_t)v * 128))[lane];
    float av[4] = {a.x, a.y, a.z, a.w};
    float hv[4] = {h.x, h.y, h.z, h.w};
    float p0 = 0.f, p1 = 0.f;
#pragma unroll
    for (int j = 0; j < 4; j++) {
        const int k = lane * 4 + j;
        const float x2 = fmaxf(fmaf(dinv, av[j] + hv[j], sb1[k]), 0.f);
        p0 = fmaf(x2, sW2[k * 2 + 0], p0);
        p1 = fmaf(x2, sW2[k * 2 + 1], p1);
    }
#pragma unroll
    for (int o = 16; o > 0; o >>= 1) {
        p0 += __shfl_xor_sync(0xffffffffu, p0, o);
        p1 += __shfl_xor_sync(0xffffffffu, p1, o);
    }
    if (lane == 0) ((float2*)g_HS2)[v] = make_float2(dinv * p0, dinv * p1);
}

// ---------------------------------------------------------------------------
// 7) scatter layer 2: ACC2[dst] += HS2[src]   (one thread per edge, float2 red)
// ---------------------------------------------------------------------------
__global__ void scatter2_kernel() {
    const int e = blockIdx.x * blockDim.x + threadIdx.x;
    if (e >= NE) return;
    const int s = g_src[e];
    const int d = g_dst[e];
    float2 v = ((const float2*)g_HS2)[s];
    atomicAdd(((float2*)g_ACC2) + d, v);
}

// 8) final: out = dinv*(ACC2+HS2) + b2
__global__ void final_kernel(const float* __restrict__ b2, float* __restrict__ out) {
    const int i = blockIdx.x * blockDim.x + threadIdx.x;
    if (i >= NN) return;
    const float dinv = g_dinv[i];
    const float2 a = ((const float2*)g_ACC2)[i];
    const float2 h = ((const float2*)g_HS2)[i];
    float2 o;
    o.x = fmaf(dinv, a.x + h.x, b2[0]);
    o.y = fmaf(dinv, a.y + h.y, b2[1]);
    ((float2*)out)[i] = o;
}

// ---------------------------------------------------------------------------
extern "C" void kernel_launch(void* const* d_in, const int* in_sizes, int n_in,
                              void* d_out, int out_size) {
    const float* x   = (const float*)d_in[0];
    const int*   ei  = (const int*)d_in[1];    // dtype resolved on device
    const float* W1  = (const float*)d_in[2];
    const float* b1  = (const float*)d_in[3];
    const float* W2  = (const float*)d_in[4];
    const float* b2  = (const float*)d_in[5];
    float* out = (float*)d_out;

    const int T = 256;
    // 0) resolve edge dtype + normalize to int32
    probe_kernel<<<1, 256>>>(ei);
    convert_kernel<<<(NE + T - 1) / T, T>>>(ei);
    // 1) init scratch
    init_kernel<<<(NN * D / 4 + T - 1) / T, T>>>();
    // 2) degrees
    deg_kernel<<<(NE + T - 1) / T, T>>>();
    // 3) dinv
    rsqrt_kernel<<<(NN + T - 1) / T, T>>>();
    // 4) HS = dinv * (X @ W1)
    gemm1_kernel<<<(NN + 127) / 128, T>>>(x, W1);
    // 5) edge scatter (layer 1), warp per edge
    scatter1_kernel<<<(int)(((long long)NE * 32 + T - 1) / T), T>>>();
    // 6) relu-epilogue + layer-2 linear, warp per node
    layer2_kernel<<<(NN * 32 + T - 1) / T, T>>>(b1, W2);
    // 7) edge scatter (layer 2), thread per edge
    scatter2_kernel<<<(NE + T - 1) / T, T>>>();
    // 8) bias + write output
    final_kernel<<<(NN + T - 1) / T, T>>>(b2, out);
}

// round 8
// speedup vs baseline: 1.7065x; 1.7065x over previous
#include <cuda_runtime.h>
#include <cstdint>
#include <cstddef>

#define NN 100000
#define NE 1600000
#define D  128
#define SCAN_B 1024
#define NBLK ((NN + SCAN_B - 1) / SCAN_B)   // 98

// Scratch (static device globals; no allocation allowed)
__device__ int   g_is64;
__device__ int   g_deg[NN];        // in-degree (no self loop)
__device__ int   g_scan[NN];       // inclusive scan within block
__device__ int   g_bsum[NBLK];
__device__ int   g_boff[NBLK];
__device__ int   g_rowstart[NN];
__device__ int   g_cursor[NN];
__device__ int   g_csr[NE];        // src ids grouped by dst
__device__ float g_dinv[NN];
__device__ float g_HS [(size_t)NN * D];   // dinv[u] * (x @ W1)[u]
__device__ float g_HS2[NN * 2];           // dinv[u] * (relu(...) @ W2)[u]

// f32x2 packed-FMA helpers (FFMA2: 2x fp32 per fma-pipe issue slot)
#define FMA_F32X2(d, a, b) \
    asm("fma.rn.f32x2 %0, %1, %2, %0;" : "+l"(d) : "l"(a), "l"(b))
#define PACK_F32X2(out, lo, hi) \
    asm("mov.b64 %0, {%1, %2};" : "=l"(out) : "r"(lo), "r"(hi))
#define UNPACK_F32X2(lo, hi, in) \
    asm("mov.b64 {%0, %1}, %2;" : "=r"(lo), "=r"(hi) : "l"(in))

// ---------------------------------------------------------------------------
// 0) zero degree array (graph is replayed; globals must be re-initialized)
// ---------------------------------------------------------------------------
__global__ void zero_kernel() {
    const int i = blockIdx.x * blockDim.x + threadIdx.x;
    if (i < NN) g_deg[i] = 0;
}

// probe edge dtype: int64 -> all odd 32-bit words are 0 (high words of idx<2^31)
__global__ void probe_kernel(const int* __restrict__ raw) {
    __shared__ int nz;
    if (threadIdx.x == 0) nz = 0;
    __syncthreads();
    const int idx = 2 * (threadIdx.x * 4096) + 1;   // < 2*NE
    if (raw[idx] != 0) atomicAdd(&nz, 1);
    __syncthreads();
    if (threadIdx.x == 0) g_is64 = (nz == 0) ? 1 : 0;
}

// 1) degree histogram on dst (reads raw buffer under either dtype)
__global__ void deg_kernel(const int* __restrict__ raw) {
    const int e = blockIdx.x * blockDim.x + threadIdx.x;
    if (e >= NE) return;
    const int d = g_is64 ? raw[2 * (NE + e)] : raw[NE + e];
    atomicAdd(&g_deg[d], 1);
}

// ---------------------------------------------------------------------------
// 2) exclusive scan of degrees -> rowstart (3 passes)
// ---------------------------------------------------------------------------
__global__ __launch_bounds__(SCAN_B) void scan1_kernel() {
    __shared__ int sh[SCAN_B];
    const int i = blockIdx.x * SCAN_B + threadIdx.x;
    sh[threadIdx.x] = (i < NN) ? g_deg[i] : 0;
    __syncthreads();
#pragma unroll
    for (int o = 1; o < SCAN_B; o <<= 1) {
        int t = (threadIdx.x >= o) ? sh[threadIdx.x - o] : 0;
        __syncthreads();
        sh[threadIdx.x] += t;
        __syncthreads();
    }
    if (i < NN) g_scan[i] = sh[threadIdx.x];
    if (threadIdx.x == SCAN_B - 1) g_bsum[blockIdx.x] = sh[threadIdx.x];
}

__global__ void scan2_kernel() {
    if (threadIdx.x == 0) {
        int acc = 0;
        for (int b = 0; b < NBLK; b++) { g_boff[b] = acc; acc += g_bsum[b]; }
    }
}

// 3) rowstart/cursor + dinv = rsqrt(deg + 1) fused
__global__ void scan3_kernel() {
    const int i = blockIdx.x * blockDim.x + threadIdx.x;
    if (i >= NN) return;
    const int dg = g_deg[i];
    const int excl = g_boff[i / SCAN_B] + g_scan[i] - dg;
    g_rowstart[i] = excl;
    g_cursor[i]   = excl;
    g_dinv[i]     = rsqrtf((float)(dg + 1));
}

// 4) CSR fill: csr[cursor[dst]++] = src
__global__ void fill_kernel(const int* __restrict__ raw) {
    const int e = blockIdx.x * blockDim.x + threadIdx.x;
    if (e >= NE) return;
    int s, d;
    if (g_is64) { s = raw[2 * e]; d = raw[2 * (NE + e)]; }
    else        { s = raw[e];     d = raw[NE + e]; }
    const int p = atomicAdd(&g_cursor[d], 1);
    g_csr[p] = s;
}

// ---------------------------------------------------------------------------
// 5) HS = dinv[:,None] * (X @ W1)   fp32, f32x2 packed FMA, 8x8/thr
// ---------------------------------------------------------------------------
__global__ __launch_bounds__(256) void gemm1_kernel(const float* __restrict__ X,
                                                    const float* __restrict__ W1) {
    __shared__ float As[16][132];   // [k][m], padded
    __shared__ float Bs[16][128];   // [k][n]
    const int tid = threadIdx.x;
    const int tx = tid & 15;
    const int ty = tid >> 4;
    const int m0 = blockIdx.x * 128;

    unsigned long long accp[8][4];  // acc[i][2j..2j+1] packed f32x2
#pragma unroll
    for (int i = 0; i < 8; i++)
#pragma unroll
        for (int j = 0; j < 4; j++) accp[i][j] = 0ull;

#pragma unroll 1
    for (int k0 = 0; k0 < 128; k0 += 16) {
        {   // X tile (128 x 16) -> As[k][m] transposed
            const int r = tid >> 2;
            const int c = (tid & 3) << 2;
#pragma unroll
            for (int rr = 0; rr < 128; rr += 64) {
                const int gr = m0 + r + rr;
                float4 v = make_float4(0.f, 0.f, 0.f, 0.f);
                if (gr < NN) v = *(const float4*)(X + (size_t)gr * 128 + k0 + c);
                As[c + 0][r + rr] = v.x;
                As[c + 1][r + rr] = v.y;
                As[c + 2][r + rr] = v.z;
                As[c + 3][r + rr] = v.w;
            }
        }
        {   // W1 tile (16 x 128)
            const int wr = tid >> 5;
            const int wc = (tid & 31) << 2;
#pragma unroll
            for (int kk = 0; kk < 16; kk += 8)
                *(float4*)&Bs[wr + kk][wc] =
                    *(const float4*)(W1 + (size_t)(k0 + wr + kk) * 128 + wc);
        }
        __syncthreads();
#pragma unroll
        for (int kk = 0; kk < 16; kk++) {
            float a[8];
            *(float4*)(a)     = *(const float4*)&As[kk][ty * 4];
            *(float4*)(a + 4) = *(const float4*)&As[kk][64 + ty * 4];
            // b pairs straight from shared (adjacent floats = one f32x2)
            ulonglong2 bq0 = *(const ulonglong2*)&Bs[kk][tx * 4];
            ulonglong2 bq1 = *(const ulonglong2*)&Bs[kk][64 + tx * 4];
            unsigned long long bp[4] = {bq0.x, bq0.y, bq1.x, bq1.y};
#pragma unroll
            for (int i = 0; i < 8; i++) {
                unsigned long long ap;
                const unsigned int au = __float_as_uint(a[i]);
                PACK_F32X2(ap, au, au);
                FMA_F32X2(accp[i][0], ap, bp[0]);
                FMA_F32X2(accp[i][1], ap, bp[1]);
                FMA_F32X2(accp[i][2], ap, bp[2]);
                FMA_F32X2(accp[i][3], ap, bp[3]);
            }
        }
        __syncthreads();
    }
    // epilogue: unpack, scale by dinv, write HS
#pragma unroll
    for (int i = 0; i < 8; i++) {
        const int gr = m0 + ((i < 4) ? (ty * 4 + i) : (64 + ty * 4 + i - 4));
        if (gr >= NN) continue;
        const float s = g_dinv[gr];
        float c[8];
#pragma unroll
        for (int j = 0; j < 4; j++) {
            unsigned int lo, hi;
            UNPACK_F32X2(lo, hi, accp[i][j]);
            c[2 * j]     = __uint_as_float(lo) * s;
            c[2 * j + 1] = __uint_as_float(hi) * s;
        }
        *(float4*)(g_HS + (size_t)gr * 128 + tx * 4)      = make_float4(c[0], c[1], c[2], c[3]);
        *(float4*)(g_HS + (size_t)gr * 128 + 64 + tx * 4) = make_float4(c[4], c[5], c[6], c[7]);
    }
}

// ---------------------------------------------------------------------------
// 6) fused layer-1 aggregation (CSR gather, register accumulation) + ReLU + W2
//    warp per node: acc = HS[v] + sum_{u->v} HS[u];  x2 = relu(dinv*acc + b1)
//    HS2[v] = dinv * (x2 @ W2)
// ---------------------------------------------------------------------------
__global__ __launch_bounds__(256) void gather_layer2_kernel(const float* __restrict__ b1,
                                                            const float* __restrict__ W2) {
    __shared__ float sW2[256];
    __shared__ float sb1[128];
    const int tid = threadIdx.x;
    if (tid < 256) sW2[tid] = W2[tid];
    if (tid < 128) sb1[tid] = b1[tid];
    __syncthreads();
    const int v = (blockIdx.x * blockDim.x + tid) >> 5;
    const int lane = tid & 31;
    if (v >= NN) return;

    float4 a = ((const float4*)(g_HS + (size_t)v * 128))[lane];   // self loop
    const int start = g_rowstart[v];
    const int deg = g_deg[v];
    for (int j = 0; j < deg; j++) {
        const int s = g_csr[start + j];
        const float4 h = ((const float4*)(g_HS + (size_t)s * 128))[lane];
        a.x += h.x; a.y += h.y; a.z += h.z; a.w += h.w;
    }
    const float dinv = g_dinv[v];
    float av[4] = {a.x, a.y, a.z, a.w};
    float p0 = 0.f, p1 = 0.f;
#pragma unroll
    for (int j = 0; j < 4; j++) {
        const int k = lane * 4 + j;
        const float x2 = fmaxf(fmaf(dinv, av[j], sb1[k]), 0.f);
        p0 = fmaf(x2, sW2[k * 2 + 0], p0);
        p1 = fmaf(x2, sW2[k * 2 + 1], p1);
    }
#pragma unroll
    for (int o = 16; o > 0; o >>= 1) {
        p0 += __shfl_xor_sync(0xffffffffu, p0, o);
        p1 += __shfl_xor_sync(0xffffffffu, p1, o);
    }
    if (lane == 0) ((float2*)g_HS2)[v] = make_float2(dinv * p0, dinv * p1);
}

// ---------------------------------------------------------------------------
// 7) fused layer-2 aggregation + bias: out = dinv*(HS2[v] + sum HS2[u]) + b2
//    warp per node, lanes stride edges
// ---------------------------------------------------------------------------
__global__ __launch_bounds__(256) void gather2_final_kernel(const float* __restrict__ b2,
                                                            float* __restrict__ out) {
    const int v = (blockIdx.x * blockDim.x + threadIdx.x) >> 5;
    const int lane = threadIdx.x & 31;
    if (v >= NN) return;
    const int start = g_rowstart[v];
    const int deg = g_deg[v];
    float2 acc = (lane == 0) ? ((const float2*)g_HS2)[v] : make_float2(0.f, 0.f);
    for (int j = lane; j < deg; j += 32) {
        const float2 h = ((const float2*)g_HS2)[g_csr[start + j]];
        acc.x += h.x; acc.y += h.y;
    }
#pragma unroll
    for (int o = 16; o > 0; o >>= 1) {
        acc.x += __shfl_xor_sync(0xffffffffu, acc.x, o);
        acc.y += __shfl_xor_sync(0xffffffffu, acc.y, o);
    }
    if (lane == 0) {
        const float dinv = g_dinv[v];
        ((float2*)out)[v] = make_float2(fmaf(dinv, acc.x, b2[0]),
                                        fmaf(dinv, acc.y, b2[1]));
    }
}

// ---------------------------------------------------------------------------
extern "C" void kernel_launch(void* const* d_in, const int* in_sizes, int n_in,
                              void* d_out, int out_size) {
    const float* x  = (const float*)d_in[0];
    const int*   ei = (const int*)d_in[1];   // dtype resolved on device
    const float* W1 = (const float*)d_in[2];
    const float* b1 = (const float*)d_in[3];
    const float* W2 = (const float*)d_in[4];
    const float* b2 = (const float*)d_in[5];
    float* out = (float*)d_out;

    const int T = 256;
    zero_kernel<<<(NN + T - 1) / T, T>>>();
    probe_kernel<<<1, 256>>>(ei);
    deg_kernel<<<(NE + T - 1) / T, T>>>(ei);
    scan1_kernel<<<NBLK, SCAN_B>>>();
    scan2_kernel<<<1, 32>>>();
    scan3_kernel<<<(NN + T - 1) / T, T>>>();
    fill_kernel<<<(NE + T - 1) / T, T>>>(ei);
    gemm1_kernel<<<(NN + 127) / 128, T>>>(x, W1);
    gather_layer2_kernel<<<(NN * 32 + T - 1) / T, T>>>(b1, W2);
    gather2_final_kernel<<<(NN * 32 + T - 1) / T, T>>>(b2, out);
}

// round 11
// speedup vs baseline: 1.8452x; 1.0813x over previous
#include <cuda_runtime.h>
#include <cuda_fp16.h>
#include <cstdint>
#include <cstddef>

#define NN 100000
#define NE 1600000
#define D  128
#define SCAN_B 1024
#define NBLK ((NN + SCAN_B - 1) / SCAN_B)   // 98

#define GEMM_BLOCKS 782                     // ceil(NN/128)
#define DEG_BLK 260
#define GRID_MERGED 1042                    // 782 gemm + 260 deg (every 4th)

// Scratch (static device globals; no allocation allowed)
__device__ int    g_is64;
__device__ int    g_deg[NN];        // in-degree (no self loop)
__device__ int    g_scan[NN];       // inclusive scan within block
__device__ int    g_bsum[NBLK];
__device__ int    g_boff[NBLK];     // exclusive block offsets
__device__ int    g_rowstart[NN];
__device__ int    g_cursor[NN];
__device__ int    g_csr[NE];        // src ids grouped by dst
__device__ float  g_dinv[NN];
__device__ __half g_HSh[(size_t)NN * D];  // fp16: dinv[u] * (x @ W1)[u]
__device__ float  g_HS2[NN * 2];          // fp32: dinv[u] * (relu(...) @ W2)[u]

// bit-cast helpers (free in SASS)
__device__ __forceinline__ unsigned int h2_as_u32(__half2 h) {
    return *reinterpret_cast<unsigned int*>(&h);
}
__device__ __forceinline__ __half2 u32_as_h2(unsigned int u) {
    return *reinterpret_cast<__half2*>(&u);
}

// f32x2 packed-FMA helpers (FFMA2: 2x fp32 per fma-pipe issue slot)
#define FMA_F32X2(d, a, b) \
    asm("fma.rn.f32x2 %0, %1, %2, %0;" : "+l"(d) : "l"(a), "l"(b))
#define PACK_F32X2(out, lo, hi) \
    asm("mov.b64 %0, {%1, %2};" : "=l"(out) : "r"(lo), "r"(hi))
#define UNPACK_F32X2(lo, hi, in) \
    asm("mov.b64 {%0, %1}, %2;" : "=r"(lo), "=r"(hi) : "l"(in))

// ---------------------------------------------------------------------------
// 0) zero degrees + (block 0) probe edge dtype.
//    int64 -> all odd 32-bit words are 0 (high words of idx < 2^31).
// ---------------------------------------------------------------------------
__global__ void zero_probe_kernel(const int* __restrict__ raw) {
    const int i = blockIdx.x * blockDim.x + threadIdx.x;
    if (i < NN) g_deg[i] = 0;
    if (blockIdx.x == 0) {
        __shared__ int nz;
        if (threadIdx.x == 0) nz = 0;
        __syncthreads();
        const int idx = 2 * (threadIdx.x * 4096) + 1;   // < 2*NE
        if (raw[idx] != 0) atomicAdd(&nz, 1);
        __syncthreads();
        if (threadIdx.x == 0) g_is64 = (nz == 0) ? 1 : 0;
    }
}

// ---------------------------------------------------------------------------
// 1) merged: GEMM (unscaled X @ W1 -> fp16 HS) co-running with the degree
//    histogram. Every 4th block is a deg block so deg work is interleaved
//    into wave 1 alongside gemm blocks (fma-bound ∥ atomic/latency-bound).
//    dinv isn't known yet; hs_scale_kernel applies it after the scan chain.
// ---------------------------------------------------------------------------
__global__ __launch_bounds__(256) void gemm_deg_kernel(const float* __restrict__ X,
                                                       const float* __restrict__ W1,
                                                       const int* __restrict__ raw) {
    const int bid = blockIdx.x;
    if ((bid & 3) == 3) {
        // ---- degree histogram role ----
        const int dbid = bid >> 2;             // 0..259
        const int is64 = g_is64;
        const int stride = DEG_BLK * 256;
        for (int e = dbid * 256 + threadIdx.x; e < NE; e += stride) {
            const int d = is64 ? raw[2 * (NE + e)] : raw[NE + e];
            atomicAdd(&g_deg[d], 1);
        }
        return;
    }
    // ---- gemm role ----
    const int tile = bid - ((bid + 1) >> 2);   // 0..781
    __shared__ float As[16][132];   // [k][m], padded
    __shared__ float Bs[16][128];   // [k][n]
    const int tid = threadIdx.x;
    const int tx = tid & 15;
    const int ty = tid >> 4;
    const int m0 = tile * 128;

    unsigned long long accp[8][4];  // acc[i][2j..2j+1] packed f32x2
#pragma unroll
    for (int i = 0; i < 8; i++)
#pragma unroll
        for (int j = 0; j < 4; j++) accp[i][j] = 0ull;

#pragma unroll 1
    for (int k0 = 0; k0 < 128; k0 += 16) {
        {   // X tile (128 x 16) -> As[k][m] transposed
            const int r = tid >> 2;
            const int c = (tid & 3) << 2;
#pragma unroll
            for (int rr = 0; rr < 128; rr += 64) {
                const int gr = m0 + r + rr;
                float4 v = make_float4(0.f, 0.f, 0.f, 0.f);
                if (gr < NN) v = *(const float4*)(X + (size_t)gr * 128 + k0 + c);
                As[c + 0][r + rr] = v.x;
                As[c + 1][r + rr] = v.y;
                As[c + 2][r + rr] = v.z;
                As[c + 3][r + rr] = v.w;
            }
        }
        {   // W1 tile (16 x 128)
            const int wr = tid >> 5;
            const int wc = (tid & 31) << 2;
#pragma unroll
            for (int kk = 0; kk < 16; kk += 8)
                *(float4*)&Bs[wr + kk][wc] =
                    *(const float4*)(W1 + (size_t)(k0 + wr + kk) * 128 + wc);
        }
        __syncthreads();
#pragma unroll
        for (int kk = 0; kk < 16; kk++) {
            float a[8];
            *(float4*)(a)     = *(const float4*)&As[kk][ty * 4];
            *(float4*)(a + 4) = *(const float4*)&As[kk][64 + ty * 4];
            ulonglong2 bq0 = *(const ulonglong2*)&Bs[kk][tx * 4];
            ulonglong2 bq1 = *(const ulonglong2*)&Bs[kk][64 + tx * 4];
            unsigned long long bp[4] = {bq0.x, bq0.y, bq1.x, bq1.y};
#pragma unroll
            for (int i = 0; i < 8; i++) {
                unsigned long long ap;
                const unsigned int au = __float_as_uint(a[i]);
                PACK_F32X2(ap, au, au);
                FMA_F32X2(accp[i][0], ap, bp[0]);
                FMA_F32X2(accp[i][1], ap, bp[1]);
                FMA_F32X2(accp[i][2], ap, bp[2]);
                FMA_F32X2(accp[i][3], ap, bp[3]);
            }
        }
        __syncthreads();
    }
    // epilogue: unpack, write UNSCALED fp16 HS (values ~N(0,1), fp16-safe)
#pragma unroll
    for (int i = 0; i < 8; i++) {
        const int gr = m0 + ((i < 4) ? (ty * 4 + i) : (64 + ty * 4 + i - 4));
        if (gr >= NN) continue;
        float c[8];
#pragma unroll
        for (int j = 0; j < 4; j++) {
            unsigned int lo, hi;
            UNPACK_F32X2(lo, hi, accp[i][j]);
            c[2 * j]     = __uint_as_float(lo);
            c[2 * j + 1] = __uint_as_float(hi);
        }
        uint2 h0, h1;
        h0.x = h2_as_u32(__floats2half2_rn(c[0], c[1]));
        h0.y = h2_as_u32(__floats2half2_rn(c[2], c[3]));
        h1.x = h2_as_u32(__floats2half2_rn(c[4], c[5]));
        h1.y = h2_as_u32(__floats2half2_rn(c[6], c[7]));
        *(uint2*)(g_HSh + (size_t)gr * 128 + tx * 4)      = h0;
        *(uint2*)(g_HSh + (size_t)gr * 128 + 64 + tx * 4) = h1;
    }
}

// 2) block-level inclusive scan of degrees
__global__ __launch_bounds__(SCAN_B) void scan1_kernel() {
    __shared__ int sh[SCAN_B];
    const int i = blockIdx.x * SCAN_B + threadIdx.x;
    sh[threadIdx.x] = (i < NN) ? g_deg[i] : 0;
    __syncthreads();
#pragma unroll
    for (int o = 1; o < SCAN_B; o <<= 1) {
        int t = (threadIdx.x >= o) ? sh[threadIdx.x - o] : 0;
        __syncthreads();
        sh[threadIdx.x] += t;
        __syncthreads();
    }
    if (i < NN) g_scan[i] = sh[threadIdx.x];
    if (threadIdx.x == SCAN_B - 1) g_bsum[blockIdx.x] = sh[threadIdx.x];
}

// 3) scan of the 98 block sums (one block, shfl)
__global__ void scan2_kernel() {
    __shared__ int ws[4];
    const int t = threadIdx.x;            // 128 threads
    const int lane = t & 31;
    const int w = t >> 5;
    int v = (t < NBLK) ? g_bsum[t] : 0;
    const int orig = v;
#pragma unroll
    for (int o = 1; o < 32; o <<= 1) {
        int n = __shfl_up_sync(0xffffffffu, v, o);
        if (lane >= o) v += n;
    }
    if (lane == 31) ws[w] = v;
    __syncthreads();
    if (w == 0) {
        int s = (lane < 4) ? ws[lane] : 0;
#pragma unroll
        for (int o = 1; o < 4; o <<= 1) {
            int n = __shfl_up_sync(0xffffffffu, s, o);
            if (lane >= o) s += n;
        }
        if (lane < 4) ws[lane] = s;
    }
    __syncthreads();
    const int incl = v + ((w > 0) ? ws[w - 1] : 0);
    if (t < NBLK) g_boff[t] = incl - orig;   // exclusive
}

// 4) rowstart/cursor + dinv = rsqrt(deg + 1)
__global__ void scan3_kernel() {
    const int i = blockIdx.x * blockDim.x + threadIdx.x;
    if (i >= NN) return;
    const int dg = g_deg[i];
    const int excl = g_boff[i / SCAN_B] + g_scan[i] - dg;
    g_rowstart[i] = excl;
    g_cursor[i]   = excl;
    g_dinv[i]     = rsqrtf((float)(dg + 1));
}

// 5a) scale HSh rows by dinv (deferred from gemm epilogue), uint2 = 4 halfs
__global__ void hs_scale_kernel() {
    const int i = blockIdx.x * blockDim.x + threadIdx.x;   // uint2 index
    const int total = NN * D / 4;
    if (i >= total) return;
    const int node = i >> 5;                // 32 uint2 per row
    const __half2 s = __float2half2_rn(g_dinv[node]);
    uint2 p = ((uint2*)g_HSh)[i];
    p.x = h2_as_u32(__hmul2(u32_as_h2(p.x), s));
    p.y = h2_as_u32(__hmul2(u32_as_h2(p.y), s));
    ((uint2*)g_HSh)[i] = p;
}

// 5b) CSR fill: csr[cursor[dst]++] = src
__global__ void fill_kernel(const int* __restrict__ raw) {
    const int e = blockIdx.x * blockDim.x + threadIdx.x;
    if (e >= NE) return;
    int s, d;
    if (g_is64) { s = raw[2 * e]; d = raw[2 * (NE + e)]; }
    else        { s = raw[e];     d = raw[NE + e]; }
    const int p = atomicAdd(&g_cursor[d], 1);
    g_csr[p] = s;
}

// ---------------------------------------------------------------------------
// 6) fused layer-1 aggregation (CSR gather over fp16 HS, fp32 accumulate)
//    + ReLU + W2:  HS2[v] = dinv * (relu(dinv*agg + b1) @ W2)
// ---------------------------------------------------------------------------
__global__ __launch_bounds__(256) void gather_layer2_kernel(const float* __restrict__ b1,
                                                            const float* __restrict__ W2) {
    __shared__ float sW2[256];
    __shared__ float sb1[128];
    const int tid = threadIdx.x;
    if (tid < 256) sW2[tid] = W2[tid];
    if (tid < 128) sb1[tid] = b1[tid];
    __syncthreads();
    const int v = (blockIdx.x * blockDim.x + tid) >> 5;
    const int lane = tid & 31;
    if (v >= NN) return;

    // self loop
    uint2 sp = *(const uint2*)(g_HSh + (size_t)v * 128 + lane * 4);
    float2 l0 = __half22float2(u32_as_h2(sp.x));
    float2 l1 = __half22float2(u32_as_h2(sp.y));
    float a0 = l0.x, a1 = l0.y, a2 = l1.x, a3 = l1.y;

    const int start = g_rowstart[v];
    const int deg = g_deg[v];
    int j = 0;
    for (; j + 2 <= deg; j += 2) {
        const int s0 = g_csr[start + j];
        const int s1 = g_csr[start + j + 1];
        const uint2 p0 = *(const uint2*)(g_HSh + (size_t)s0 * 128 + lane * 4);
        const uint2 p1 = *(const uint2*)(g_HSh + (size_t)s1 * 128 + lane * 4);
        float2 q;
        q = __half22float2(u32_as_h2(p0.x)); a0 += q.x; a1 += q.y;
        q = __half22float2(u32_as_h2(p0.y)); a2 += q.x; a3 += q.y;
        q = __half22float2(u32_as_h2(p1.x)); a0 += q.x; a1 += q.y;
        q = __half22float2(u32_as_h2(p1.y)); a2 += q.x; a3 += q.y;
    }
    if (j < deg) {
        const int s0 = g_csr[start + j];
        const uint2 p0 = *(const uint2*)(g_HSh + (size_t)s0 * 128 + lane * 4);
        float2 q;
        q = __half22float2(u32_as_h2(p0.x)); a0 += q.x; a1 += q.y;
        q = __half22float2(u32_as_h2(p0.y)); a2 += q.x; a3 += q.y;
    }

    const float dinv = g_dinv[v];
    const float av[4] = {a0, a1, a2, a3};
    float p0 = 0.f, p1 = 0.f;
#pragma unroll
    for (int jj = 0; jj < 4; jj++) {
        const int k = lane * 4 + jj;
        const float x2 = fmaxf(fmaf(dinv, av[jj], sb1[k]), 0.f);
        p0 = fmaf(x2, sW2[k * 2 + 0], p0);
        p1 = fmaf(x2, sW2[k * 2 + 1], p1);
    }
#pragma unroll
    for (int o = 16; o > 0; o >>= 1) {
        p0 += __shfl_xor_sync(0xffffffffu, p0, o);
        p1 += __shfl_xor_sync(0xffffffffu, p1, o);
    }
    if (lane == 0) ((float2*)g_HS2)[v] = make_float2(dinv * p0, dinv * p1);
}

// ---------------------------------------------------------------------------
// 7) fused layer-2 aggregation + bias (fp32, tiny traffic)
// ---------------------------------------------------------------------------
__global__ __launch_bounds__(256) void gather2_final_kernel(const float* __restrict__ b2,
                                                            float* __restrict__ out) {
    const int v = (blockIdx.x * blockDim.x + threadIdx.x) >> 5;
    const int lane = threadIdx.x & 31;
    if (v >= NN) return;
    const int start = g_rowstart[v];
    const int deg = g_deg[v];
    float2 acc = (lane == 0) ? ((const float2*)g_HS2)[v] : make_float2(0.f, 0.f);
    for (int j = lane; j < deg; j += 32) {
        const float2 h = ((const float2*)g_HS2)[g_csr[start + j]];
        acc.x += h.x; acc.y += h.y;
    }
#pragma unroll
    for (int o = 16; o > 0; o >>= 1) {
        acc.x += __shfl_xor_sync(0xffffffffu, acc.x, o);
        acc.y += __shfl_xor_sync(0xffffffffu, acc.y, o);
    }
    if (lane == 0) {
        const float dinv = g_dinv[v];
        ((float2*)out)[v] = make_float2(fmaf(dinv, acc.x, b2[0]),
                                        fmaf(dinv, acc.y, b2[1]));
    }
}

// ---------------------------------------------------------------------------
extern "C" void kernel_launch(void* const* d_in, const int* in_sizes, int n_in,
                              void* d_out, int out_size) {
    const float* x  = (const float*)d_in[0];
    const int*   ei = (const int*)d_in[1];   // dtype resolved on device
    const float* W1 = (const float*)d_in[2];
    const float* b1 = (const float*)d_in[3];
    const float* W2 = (const float*)d_in[4];
    const float* b2 = (const float*)d_in[5];
    float* out = (float*)d_out;

    const int T = 256;
    zero_probe_kernel<<<(NN + T - 1) / T, T>>>(ei);
    gemm_deg_kernel<<<GRID_MERGED, T>>>(x, W1, ei);     // gemm (unscaled HS) ∥ deg
    scan1_kernel<<<NBLK, SCAN_B>>>();
    scan2_kernel<<<1, 128>>>();
    scan3_kernel<<<(NN + T - 1) / T, T>>>();
    hs_scale_kernel<<<(NN * D / 4 + T - 1) / T, T>>>(); // apply dinv to HS
    fill_kernel<<<(NE + T - 1) / T, T>>>(ei);
    gather_layer2_kernel<<<(NN * 32 + T - 1) / T, T>>>(b1, W2);
    gather2_final_kernel<<<(NN * 32 + T - 1) / T, T>>>(b2, out);
}

// round 12
// speedup vs baseline: 1.9704x; 1.0679x over previous
#include <cuda_runtime.h>
#include <cuda_fp16.h>
#include <cstdint>
#include <cstddef>

#define NN 100000
#define NE 1600000
#define D  128
#define SCAN_B 1024
#define NBLK ((NN + SCAN_B - 1) / SCAN_B)   // 98

// Scratch (static device globals; no allocation allowed)
__device__ int    g_is64;
__device__ int    g_deg[NN];        // in-degree (no self loop)
__device__ int    g_scan[NN];       // inclusive scan within block
__device__ int    g_bsum[NBLK];
__device__ int    g_boff[NBLK];     // exclusive block offsets
__device__ int    g_rowstart[NN];
__device__ int    g_cursor[NN];
__device__ int    g_csr[NE];        // src ids grouped by dst
__device__ float  g_dinv[NN];
__device__ __half g_HSh[(size_t)NN * D];  // fp16: UNSCALED (x @ W1)[u]
__device__ float  g_HS2[NN * 2];          // fp32: dinv[u] * (relu(...) @ W2)[u]

// bit-cast helpers (free in SASS)
__device__ __forceinline__ unsigned int h2_as_u32(__half2 h) {
    return *reinterpret_cast<unsigned int*>(&h);
}
__device__ __forceinline__ __half2 u32_as_h2(unsigned int u) {
    return *reinterpret_cast<__half2*>(&u);
}

// f32x2 packed-FMA helpers (FFMA2: 2x fp32 per fma-pipe issue slot)
#define FMA_F32X2(d, a, b) \
    asm("fma.rn.f32x2 %0, %1, %2, %0;" : "+l"(d) : "l"(a), "l"(b))
#define PACK_F32X2(out, lo, hi) \
    asm("mov.b64 %0, {%1, %2};" : "=l"(out) : "r"(lo), "r"(hi))
#define UNPACK_F32X2(lo, hi, in) \
    asm("mov.b64 {%0, %1}, %2;" : "=r"(lo), "=r"(hi) : "l"(in))

// ---------------------------------------------------------------------------
// 0) zero degrees + (block 0) probe edge dtype.
//    int64 -> all odd 32-bit words are 0 (high words of idx < 2^31).
// ---------------------------------------------------------------------------
__global__ void zero_probe_kernel(const int* __restrict__ raw) {
    const int i = blockIdx.x * blockDim.x + threadIdx.x;
    if (i < NN) g_deg[i] = 0;
    if (blockIdx.x == 0) {
        __shared__ int nz;
        if (threadIdx.x == 0) nz = 0;
        __syncthreads();
        const int idx = 2 * (threadIdx.x * 4096) + 1;   // < 2*NE
        if (raw[idx] != 0) atomicAdd(&nz, 1);
        __syncthreads();
        if (threadIdx.x == 0) g_is64 = (nz == 0) ? 1 : 0;
    }
}

// ---------------------------------------------------------------------------
// side chain 1) degree histogram on dst
// ---------------------------------------------------------------------------
__global__ void deg_kernel(const int* __restrict__ raw) {
    const int e = blockIdx.x * blockDim.x + threadIdx.x;
    if (e >= NE) return;
    const int d = g_is64 ? raw[2 * (NE + e)] : raw[NE + e];
    atomicAdd(&g_deg[d], 1);
}

// side chain 2) block-level inclusive scan of degrees
__global__ __launch_bounds__(SCAN_B) void scan1_kernel() {
    __shared__ int sh[SCAN_B];
    const int i = blockIdx.x * SCAN_B + threadIdx.x;
    sh[threadIdx.x] = (i < NN) ? g_deg[i] : 0;
    __syncthreads();
#pragma unroll
    for (int o = 1; o < SCAN_B; o <<= 1) {
        int t = (threadIdx.x >= o) ? sh[threadIdx.x - o] : 0;
        __syncthreads();
        sh[threadIdx.x] += t;
        __syncthreads();
    }
    if (i < NN) g_scan[i] = sh[threadIdx.x];
    if (threadIdx.x == SCAN_B - 1) g_bsum[blockIdx.x] = sh[threadIdx.x];
}

// side chain 3) scan of the 98 block sums (one block, shfl)
__global__ void scan2_kernel() {
    __shared__ int ws[4];
    const int t = threadIdx.x;            // 128 threads
    const int lane = t & 31;
    const int w = t >> 5;
    int v = (t < NBLK) ? g_bsum[t] : 0;
    const int orig = v;
#pragma unroll
    for (int o = 1; o < 32; o <<= 1) {
        int n = __shfl_up_sync(0xffffffffu, v, o);
        if (lane >= o) v += n;
    }
    if (lane == 31) ws[w] = v;
    __syncthreads();
    if (w == 0) {
        int s = (lane < 4) ? ws[lane] : 0;
#pragma unroll
        for (int o = 1; o < 4; o <<= 1) {
            int n = __shfl_up_sync(0xffffffffu, s, o);
            if (lane >= o) s += n;
        }
        if (lane < 4) ws[lane] = s;
    }
    __syncthreads();
    const int incl = v + ((w > 0) ? ws[w - 1] : 0);
    if (t < NBLK) g_boff[t] = incl - orig;   // exclusive
}

// side chain 4) rowstart/cursor + dinv = rsqrt(deg + 1)
__global__ void scan3_kernel() {
    const int i = blockIdx.x * blockDim.x + threadIdx.x;
    if (i >= NN) return;
    const int dg = g_deg[i];
    const int excl = g_boff[i / SCAN_B] + g_scan[i] - dg;
    g_rowstart[i] = excl;
    g_cursor[i]   = excl;
    g_dinv[i]     = rsqrtf((float)(dg + 1));
}

// side chain 5) CSR fill: csr[cursor[dst]++] = src
__global__ void fill_kernel(const int* __restrict__ raw) {
    const int e = blockIdx.x * blockDim.x + threadIdx.x;
    if (e >= NE) return;
    int s, d;
    if (g_is64) { s = raw[2 * e]; d = raw[2 * (NE + e)]; }
    else        { s = raw[e];     d = raw[NE + e]; }
    const int p = atomicAdd(&g_cursor[d], 1);
    g_csr[p] = s;
}

// ---------------------------------------------------------------------------
// main 1) GEMM: HSh = fp16(X @ W1), UNSCALED (dinv applied in the gather).
//    fp32 with f32x2 packed FMA, BM=128 BN=128 BK=16, 8x8/thread.
//    Runs concurrently with the side chain (no dependency on deg/dinv).
// ---------------------------------------------------------------------------
__global__ __launch_bounds__(256) void gemm1_kernel(const float* __restrict__ X,
                                                    const float* __restrict__ W1) {
    __shared__ float As[16][132];   // [k][m], padded
    __shared__ float Bs[16][128];   // [k][n]
    const int tid = threadIdx.x;
    const int tx = tid & 15;
    const int ty = tid >> 4;
    const int m0 = blockIdx.x * 128;

    unsigned long long accp[8][4];  // acc[i][2j..2j+1] packed f32x2
#pragma unroll
    for (int i = 0; i < 8; i++)
#pragma unroll
        for (int j = 0; j < 4; j++) accp[i][j] = 0ull;

#pragma unroll 1
    for (int k0 = 0; k0 < 128; k0 += 16) {
        {   // X tile (128 x 16) -> As[k][m] transposed
            const int r = tid >> 2;
            const int c = (tid & 3) << 2;
#pragma unroll
            for (int rr = 0; rr < 128; rr += 64) {
                const int gr = m0 + r + rr;
                float4 v = make_float4(0.f, 0.f, 0.f, 0.f);
                if (gr < NN) v = *(const float4*)(X + (size_t)gr * 128 + k0 + c);
                As[c + 0][r + rr] = v.x;
                As[c + 1][r + rr] = v.y;
                As[c + 2][r + rr] = v.z;
                As[c + 3][r + rr] = v.w;
            }
        }
        {   // W1 tile (16 x 128)
            const int wr = tid >> 5;
            const int wc = (tid & 31) << 2;
#pragma unroll
            for (int kk = 0; kk < 16; kk += 8)
                *(float4*)&Bs[wr + kk][wc] =
                    *(const float4*)(W1 + (size_t)(k0 + wr + kk) * 128 + wc);
        }
        __syncthreads();
#pragma unroll
        for (int kk = 0; kk < 16; kk++) {
            float a[8];
            *(float4*)(a)     = *(const float4*)&As[kk][ty * 4];
            *(float4*)(a + 4) = *(const float4*)&As[kk][64 + ty * 4];
            ulonglong2 bq0 = *(const ulonglong2*)&Bs[kk][tx * 4];
            ulonglong2 bq1 = *(const ulonglong2*)&Bs[kk][64 + tx * 4];
            unsigned long long bp[4] = {bq0.x, bq0.y, bq1.x, bq1.y};
#pragma unroll
            for (int i = 0; i < 8; i++) {
                unsigned long long ap;
                const unsigned int au = __float_as_uint(a[i]);
                PACK_F32X2(ap, au, au);
                FMA_F32X2(accp[i][0], ap, bp[0]);
                FMA_F32X2(accp[i][1], ap, bp[1]);
                FMA_F32X2(accp[i][2], ap, bp[2]);
                FMA_F32X2(accp[i][3], ap, bp[3]);
            }
        }
        __syncthreads();
    }
    // epilogue: unpack, write UNSCALED fp16 HS (values ~N(0,1), fp16-safe)
#pragma unroll
    for (int i = 0; i < 8; i++) {
        const int gr = m0 + ((i < 4) ? (ty * 4 + i) : (64 + ty * 4 + i - 4));
        if (gr >= NN) continue;
        float c[8];
#pragma unroll
        for (int j = 0; j < 4; j++) {
            unsigned int lo, hi;
            UNPACK_F32X2(lo, hi, accp[i][j]);
            c[2 * j]     = __uint_as_float(lo);
            c[2 * j + 1] = __uint_as_float(hi);
        }
        uint2 h0, h1;
        h0.x = h2_as_u32(__floats2half2_rn(c[0], c[1]));
        h0.y = h2_as_u32(__floats2half2_rn(c[2], c[3]));
        h1.x = h2_as_u32(__floats2half2_rn(c[4], c[5]));
        h1.y = h2_as_u32(__floats2half2_rn(c[6], c[7]));
        *(uint2*)(g_HSh + (size_t)gr * 128 + tx * 4)      = h0;
        *(uint2*)(g_HSh + (size_t)gr * 128 + 64 + tx * 4) = h1;
    }
}

// ---------------------------------------------------------------------------
// 2) fused layer-1 aggregation (CSR gather over fp16 HS, fp32 accumulate,
//    dinv[src] folded in as broadcast-load + FMA) + ReLU + W2.
//    agg = dinv[v]*h[v] + sum dinv[s]*h[s];  HS2 = dinv*(relu(dinv*agg+b1)@W2)
// ---------------------------------------------------------------------------
__global__ __launch_bounds__(256) void gather_layer2_kernel(const float* __restrict__ b1,
                                                            const float* __restrict__ W2) {
    __shared__ float sW2[256];
    __shared__ float sb1[128];
    const int tid = threadIdx.x;
    if (tid < 256) sW2[tid] = W2[tid];
    if (tid < 128) sb1[tid] = b1[tid];
    __syncthreads();
    const int v = (blockIdx.x * blockDim.x + tid) >> 5;
    const int lane = tid & 31;
    if (v >= NN) return;

    const float dinv = g_dinv[v];

    // self loop: dinv[v] * h[v]
    uint2 sp = *(const uint2*)(g_HSh + (size_t)v * 128 + lane * 4);
    float2 l0 = __half22float2(u32_as_h2(sp.x));
    float2 l1 = __half22float2(u32_as_h2(sp.y));
    float a0 = dinv * l0.x, a1 = dinv * l0.y, a2 = dinv * l1.x, a3 = dinv * l1.y;

    const int start = g_rowstart[v];
    const int deg = g_deg[v];
    int j = 0;
    for (; j + 2 <= deg; j += 2) {
        const int s0 = g_csr[start + j];
        const int s1 = g_csr[start + j + 1];
        const float w0 = __ldg(&g_dinv[s0]);     // uniform across warp -> 1 wavefront
        const float w1 = __ldg(&g_dinv[s1]);
        const uint2 p0 = *(const uint2*)(g_HSh + (size_t)s0 * 128 + lane * 4);
        const uint2 p1 = *(const uint2*)(g_HSh + (size_t)s1 * 128 + lane * 4);
        float2 q;
        q = __half22float2(u32_as_h2(p0.x)); a0 = fmaf(w0, q.x, a0); a1 = fmaf(w0, q.y, a1);
        q = __half22float2(u32_as_h2(p0.y)); a2 = fmaf(w0, q.x, a2); a3 = fmaf(w0, q.y, a3);
        q = __half22float2(u32_as_h2(p1.x)); a0 = fmaf(w1, q.x, a0); a1 = fmaf(w1, q.y, a1);
        q = __half22float2(u32_as_h2(p1.y)); a2 = fmaf(w1, q.x, a2); a3 = fmaf(w1, q.y, a3);
    }
    if (j < deg) {
        const int s0 = g_csr[start + j];
        const float w0 = __ldg(&g_dinv[s0]);
        const uint2 p0 = *(const uint2*)(g_HSh + (size_t)s0 * 128 + lane * 4);
        float2 q;
        q = __half22float2(u32_as_h2(p0.x)); a0 = fmaf(w0, q.x, a0); a1 = fmaf(w0, q.y, a1);
        q = __half22float2(u32_as_h2(p0.y)); a2 = fmaf(w0, q.x, a2); a3 = fmaf(w0, q.y, a3);
    }

    const float av[4] = {a0, a1, a2, a3};
    float p0 = 0.f, p1 = 0.f;
#pragma unroll
    for (int jj = 0; jj < 4; jj++) {
        const int k = lane * 4 + jj;
        const float x2 = fmaxf(fmaf(dinv, av[jj], sb1[k]), 0.f);
        p0 = fmaf(x2, sW2[k * 2 + 0], p0);
        p1 = fmaf(x2, sW2[k * 2 + 1], p1);
    }
#pragma unroll
    for (int o = 16; o > 0; o >>= 1) {
        p0 += __shfl_xor_sync(0xffffffffu, p0, o);
        p1 += __shfl_xor_sync(0xffffffffu, p1, o);
    }
    if (lane == 0) ((float2*)g_HS2)[v] = make_float2(dinv * p0, dinv * p1);
}

// ---------------------------------------------------------------------------
// 3) fused layer-2 aggregation + bias (fp32, tiny traffic)
// ---------------------------------------------------------------------------
__global__ __launch_bounds__(256) void gather2_final_kernel(const float* __restrict__ b2,
                                                            float* __restrict__ out) {
    const int v = (blockIdx.x * blockDim.x + threadIdx.x) >> 5;
    const int lane = threadIdx.x & 31;
    if (v >= NN) return;
    const int start = g_rowstart[v];
    const int deg = g_deg[v];
    float2 acc = (lane == 0) ? ((const float2*)g_HS2)[v] : make_float2(0.f, 0.f);
    for (int j = lane; j < deg; j += 32) {
        const float2 h = ((const float2*)g_HS2)[g_csr[start + j]];
        acc.x += h.x; acc.y += h.y;
    }
#pragma unroll
    for (int o = 16; o > 0; o >>= 1) {
        acc.x += __shfl_xor_sync(0xffffffffu, acc.x, o);
        acc.y += __shfl_xor_sync(0xffffffffu, acc.y, o);
    }
    if (lane == 0) {
        const float dinv = g_dinv[v];
        ((float2*)out)[v] = make_float2(fmaf(dinv, acc.x, b2[0]),
                                        fmaf(dinv, acc.y, b2[1]));
    }
}

// ---------------------------------------------------------------------------
extern "C" void kernel_launch(void* const* d_in, const int* in_sizes, int n_in,
                              void* d_out, int out_size) {
    const float* x  = (const float*)d_in[0];
    const int*   ei = (const int*)d_in[1];   // dtype resolved on device
    const float* W1 = (const float*)d_in[2];
    const float* b1 = (const float*)d_in[3];
    const float* W2 = (const float*)d_in[4];
    const float* b2 = (const float*)d_in[5];
    float* out = (float*)d_out;

    // One-time host objects (created on the first, uncaptured call; reused
    // identically on every call — no device memory involved).
    static cudaStream_t s_side = nullptr;
    static cudaEvent_t ev_fork = nullptr, ev_join = nullptr;
    if (s_side == nullptr) {
        cudaStreamCreateWithFlags(&s_side, cudaStreamNonBlocking);
        cudaEventCreateWithFlags(&ev_fork, cudaEventDisableTiming);
        cudaEventCreateWithFlags(&ev_join, cudaEventDisableTiming);
    }

    const int T = 256;
    // main stream: zero + probe (both branches depend on it)
    zero_probe_kernel<<<(NN + T - 1) / T, T>>>(ei);
    cudaEventRecord(ev_fork, 0);
    cudaStreamWaitEvent(s_side, ev_fork, 0);

    // side stream: CSR build chain (deg -> scan -> fill), ~46us
    deg_kernel  <<<(NE + T - 1) / T, T, 0, s_side>>>(ei);
    scan1_kernel<<<NBLK, SCAN_B, 0, s_side>>>();
    scan2_kernel<<<1, 128, 0, s_side>>>();
    scan3_kernel<<<(NN + T - 1) / T, T, 0, s_side>>>();
    fill_kernel <<<(NE + T - 1) / T, T, 0, s_side>>>(ei);
    cudaEventRecord(ev_join, s_side);

    // main stream: GEMM runs concurrently with the side chain (~60us)
    gemm1_kernel<<<(NN + 127) / 128, T>>>(x, W1);

    // join, then the gathers (need HS + csr + dinv)
    cudaStreamWaitEvent(0, ev_join, 0);
    gather_layer2_kernel<<<(NN * 32 + T - 1) / T, T>>>(b1, W2);
    gather2_final_kernel<<<(NN * 32 + T - 1) / T, T>>>(b2, out);
}

// round 16
// speedup vs baseline: 2.3956x; 1.2158x over previous
#include <cuda_runtime.h>
#include <cuda_fp16.h>
#include <mma.h>
#include <cstdint>
#include <cstddef>

using namespace nvcuda;

#define NN 100000
#define NE 1600000
#define D  128
#define SCAN_B 1024
#define NBLK ((NN + SCAN_B - 1) / SCAN_B)   // 98
#define NTILE ((NN + 127) / 128)            // 782

// Scratch (static device globals; no allocation allowed)
__device__ int    g_is64;
__device__ int    g_deg[NN];
__device__ int    g_scan[NN];
__device__ int    g_bsum[NBLK];
__device__ int    g_boff[NBLK];
__device__ int    g_rowstart[NN];
__device__ int    g_cursor[NN];
__device__ int    g_csr[NE];
__device__ float  g_dinv[NN];
__device__ __half g_W1h[D * D];            // W1^T in fp16, [N=128][K=128]
__device__ __half g_HSh[(size_t)NN * D];   // fp16: UNSCALED (x @ W1)[u]
__device__ float  g_HS2[NN * 2];

// bit-cast helpers
__device__ __forceinline__ unsigned int h2_as_u32(__half2 h) {
    return *reinterpret_cast<unsigned int*>(&h);
}
__device__ __forceinline__ __half2 u32_as_h2(unsigned int u) {
    return *reinterpret_cast<__half2*>(&u);
}

// GEMM smem geometry: A/B staged as 128 rows x 136 halves (padded, ldm%8==0;
// 8-phase bank stagger), fp32 C reuses the same space afterwards.
#define APAD 136
#define SM_A_OFF 0
#define SM_B_OFF (128 * APAD * 2)                 // 34816
#define SM_GEMM_TOT (2 * 128 * APAD * 2)          // 69632 (>= 64KB C buffer)

// ---------------------------------------------------------------------------
// 0) zero degrees + (block 0) probe edge dtype.
//    int64 -> all odd 32-bit words are 0 (high words of idx < 2^31).
// ---------------------------------------------------------------------------
__global__ void zero_probe_kernel(const int* __restrict__ raw) {
    const int i = blockIdx.x * blockDim.x + threadIdx.x;
    if (i < NN) g_deg[i] = 0;
    if (blockIdx.x == 0) {
        __shared__ int nz;
        if (threadIdx.x == 0) nz = 0;
        __syncthreads();
        const int idx = 2 * (threadIdx.x * 4096) + 1;   // < 2*NE
        if (raw[idx] != 0) atomicAdd(&nz, 1);
        __syncthreads();
        if (threadIdx.x == 0) g_is64 = (nz == 0) ? 1 : 0;
    }
}

// ----- side chain: deg -> scan -> fill -------------------------------------
__global__ void deg_kernel(const int* __restrict__ raw) {
    const int e = blockIdx.x * blockDim.x + threadIdx.x;
    if (e >= NE) return;
    const int d = g_is64 ? raw[2 * (NE + e)] : raw[NE + e];
    atomicAdd(&g_deg[d], 1);
}

__global__ __launch_bounds__(SCAN_B) void scan1_kernel() {
    __shared__ int sh[SCAN_B];
    const int i = blockIdx.x * SCAN_B + threadIdx.x;
    sh[threadIdx.x] = (i < NN) ? g_deg[i] : 0;
    __syncthreads();
#pragma unroll
    for (int o = 1; o < SCAN_B; o <<= 1) {
        int t = (threadIdx.x >= o) ? sh[threadIdx.x - o] : 0;
        __syncthreads();
        sh[threadIdx.x] += t;
        __syncthreads();
    }
    if (i < NN) g_scan[i] = sh[threadIdx.x];
    if (threadIdx.x == SCAN_B - 1) g_bsum[blockIdx.x] = sh[threadIdx.x];
}

__global__ void scan2_kernel() {
    __shared__ int ws[4];
    const int t = threadIdx.x;            // 128 threads
    const int lane = t & 31;
    const int w = t >> 5;
    int v = (t < NBLK) ? g_bsum[t] : 0;
    const int orig = v;
#pragma unroll
    for (int o = 1; o < 32; o <<= 1) {
        int n = __shfl_up_sync(0xffffffffu, v, o);
        if (lane >= o) v += n;
    }
    if (lane == 31) ws[w] = v;
    __syncthreads();
    if (w == 0) {
        int s = (lane < 4) ? ws[lane] : 0;
#pragma unroll
        for (int o = 1; o < 4; o <<= 1) {
            int n = __shfl_up_sync(0xffffffffu, s, o);
            if (lane >= o) s += n;
        }
        if (lane < 4) ws[lane] = s;
    }
    __syncthreads();
    const int incl = v + ((w > 0) ? ws[w - 1] : 0);
    if (t < NBLK) g_boff[t] = incl - orig;   // exclusive
}

__global__ void scan3_kernel() {
    const int i = blockIdx.x * blockDim.x + threadIdx.x;
    if (i >= NN) return;
    const int dg = g_deg[i];
    const int excl = g_boff[i / SCAN_B] + g_scan[i] - dg;
    g_rowstart[i] = excl;
    g_cursor[i]   = excl;
    g_dinv[i]     = rsqrtf((float)(dg + 1));
}

__global__ void fill_kernel(const int* __restrict__ raw) {
    const int e = blockIdx.x * blockDim.x + threadIdx.x;
    if (e >= NE) return;
    int s, d;
    if (g_is64) { s = raw[2 * e]; d = raw[2 * (NE + e)]; }
    else        { s = raw[e];     d = raw[NE + e]; }
    const int p = atomicAdd(&g_cursor[d], 1);
    g_csr[p] = s;
}

// ---------------------------------------------------------------------------
// main 1a) W1^T -> fp16 (once, tiny): g_W1h[n][k] = W1[k][n]
// ---------------------------------------------------------------------------
__global__ void w1t_kernel(const float* __restrict__ W1) {
    const int i = blockIdx.x * blockDim.x + threadIdx.x;   // 16384
    if (i >= D * D) return;
    const int k = i >> 7, n = i & 127;
    g_W1h[n * 128 + k] = __float2half(W1[k * 128 + n]);    // coalesced read
}

// ---------------------------------------------------------------------------
// main 1b) wmma fp16 GEMM: HSh = fp16(X @ W1), 128x128x128 tile per block.
//   8 warps in a 2(M) x 4(N) grid; each warp owns a 64x32 tile = 4x2 wmma
//   m16n16k16 fragments, fp32 accumulate. A row-major (X, converted fp32->
//   fp16 while staging), B col_major = g_W1h[n][k] (K-contiguous). C goes
//   through smem (reusing the A/B staging space) for a coalesced fp16 store.
// ---------------------------------------------------------------------------
__global__ __launch_bounds__(256) void mma_gemm_kernel(const float* __restrict__ X) {
    extern __shared__ char smem[];
    __half* As = (__half*)(smem + SM_A_OFF);
    __half* Bs = (__half*)(smem + SM_B_OFF);
    const int tid = threadIdx.x;
    const int wid = tid >> 5;
    const int wm = wid & 1;          // 0..1  (64-row slab)
    const int wn = wid >> 1;         // 0..3  (32-col slab)
    const int m0 = blockIdx.x * 128;

    // ---- stage A: X fp32 -> fp16, rows padded to APAD halves ----
#pragma unroll
    for (int i = tid; i < 128 * 32; i += 256) {      // float4 chunks
        const int r = i >> 5;
        const int c4 = (i & 31) << 2;
        const int gr = m0 + r;
        float4 v = make_float4(0.f, 0.f, 0.f, 0.f);
        if (gr < NN) v = *(const float4*)(X + (size_t)gr * 128 + c4);
        const __half2 h0 = __floats2half2_rn(v.x, v.y);
        const __half2 h1 = __floats2half2_rn(v.z, v.w);
        *(uint2*)(As + r * APAD + c4) = make_uint2(h2_as_u32(h0), h2_as_u32(h1));
    }
    // ---- stage B: g_W1h rows -> padded smem ----
#pragma unroll
    for (int i = tid; i < 128 * 16; i += 256) {      // uint4 chunks (8 halves)
        const int r = i >> 4;
        const int c8 = (i & 15) << 3;
        *(uint4*)(Bs + r * APAD + c8) = *(const uint4*)(g_W1h + r * 128 + c8);
    }
    __syncthreads();

    // ---- wmma mainloop ----
    wmma::fragment<wmma::accumulator, 16, 16, 16, float> acc[4][2];
#pragma unroll
    for (int mi = 0; mi < 4; mi++)
#pragma unroll
        for (int ni = 0; ni < 2; ni++) wmma::fill_fragment(acc[mi][ni], 0.f);

#pragma unroll
    for (int kk = 0; kk < 8; kk++) {
        wmma::fragment<wmma::matrix_a, 16, 16, 16, __half, wmma::row_major> af[4];
        wmma::fragment<wmma::matrix_b, 16, 16, 16, __half, wmma::col_major> bf[2];
#pragma unroll
        for (int mi = 0; mi < 4; mi++)
            wmma::load_matrix_sync(af[mi], As + (wm * 64 + mi * 16) * APAD + kk * 16, APAD);
#pragma unroll
        for (int ni = 0; ni < 2; ni++)
            wmma::load_matrix_sync(bf[ni], Bs + (wn * 32 + ni * 16) * APAD + kk * 16, APAD);
#pragma unroll
        for (int mi = 0; mi < 4; mi++)
#pragma unroll
            for (int ni = 0; ni < 2; ni++)
                wmma::mma_sync(acc[mi][ni], af[mi], bf[ni], acc[mi][ni]);
    }
    __syncthreads();                 // done reading As/Bs; reuse as fp32 C

    float* Cs = (float*)smem;        // 128 x 128 fp32 = 64KB <= 68KB
#pragma unroll
    for (int mi = 0; mi < 4; mi++)
#pragma unroll
        for (int ni = 0; ni < 2; ni++)
            wmma::store_matrix_sync(Cs + (wm * 64 + mi * 16) * 128 + wn * 32 + ni * 16,
                                    acc[mi][ni], 128, wmma::mem_row_major);
    __syncthreads();

    // ---- fp32 C -> fp16 HS, coalesced ----
#pragma unroll
    for (int i = tid; i < 128 * 16; i += 256) {      // 8-float chunks
        const int r = i >> 4;
        const int c8 = (i & 15) << 3;
        const int gr = m0 + r;
        if (gr >= NN) continue;
        const float4 v0 = *(const float4*)(Cs + r * 128 + c8);
        const float4 v1 = *(const float4*)(Cs + r * 128 + c8 + 4);
        uint4 o;
        o.x = h2_as_u32(__floats2half2_rn(v0.x, v0.y));
        o.y = h2_as_u32(__floats2half2_rn(v0.z, v0.w));
        o.z = h2_as_u32(__floats2half2_rn(v1.x, v1.y));
        o.w = h2_as_u32(__floats2half2_rn(v1.z, v1.w));
        *(uint4*)(g_HSh + (size_t)gr * 128 + c8) = o;
    }
}

// ---------------------------------------------------------------------------
// 2) fused layer-1 aggregation (CSR gather over fp16 HS, fp32 accumulate,
//    dinv[src] folded in) + ReLU + W2
// ---------------------------------------------------------------------------
__global__ __launch_bounds__(256) void gather_layer2_kernel(const float* __restrict__ b1,
                                                            const float* __restrict__ W2) {
    __shared__ float sW2[256];
    __shared__ float sb1[128];
    const int tid = threadIdx.x;
    if (tid < 256) sW2[tid] = W2[tid];
    if (tid < 128) sb1[tid] = b1[tid];
    __syncthreads();
    const int v = (blockIdx.x * blockDim.x + tid) >> 5;
    const int lane = tid & 31;
    if (v >= NN) return;

    const float dinv = g_dinv[v];

    uint2 sp = *(const uint2*)(g_HSh + (size_t)v * 128 + lane * 4);
    float2 l0 = __half22float2(u32_as_h2(sp.x));
    float2 l1 = __half22float2(u32_as_h2(sp.y));
    float a0 = dinv * l0.x, a1 = dinv * l0.y, a2 = dinv * l1.x, a3 = dinv * l1.y;

    const int start = g_rowstart[v];
    const int deg = g_deg[v];
    int j = 0;
    for (; j + 2 <= deg; j += 2) {
        const int s0 = g_csr[start + j];
        const int s1 = g_csr[start + j + 1];
        const float w0 = __ldg(&g_dinv[s0]);
        const float w1 = __ldg(&g_dinv[s1]);
        const uint2 p0 = *(const uint2*)(g_HSh + (size_t)s0 * 128 + lane * 4);
        const uint2 p1 = *(const uint2*)(g_HSh + (size_t)s1 * 128 + lane * 4);
        float2 q;
        q = __half22float2(u32_as_h2(p0.x)); a0 = fmaf(w0, q.x, a0); a1 = fmaf(w0, q.y, a1);
        q = __half22float2(u32_as_h2(p0.y)); a2 = fmaf(w0, q.x, a2); a3 = fmaf(w0, q.y, a3);
        q = __half22float2(u32_as_h2(p1.x)); a0 = fmaf(w1, q.x, a0); a1 = fmaf(w1, q.y, a1);
        q = __half22float2(u32_as_h2(p1.y)); a2 = fmaf(w1, q.x, a2); a3 = fmaf(w1, q.y, a3);
    }
    if (j < deg) {
        const int s0 = g_csr[start + j];
        const float w0 = __ldg(&g_dinv[s0]);
        const uint2 p0 = *(const uint2*)(g_HSh + (size_t)s0 * 128 + lane * 4);
        float2 q;
        q = __half22float2(u32_as_h2(p0.x)); a0 = fmaf(w0, q.x, a0); a1 = fmaf(w0, q.y, a1);
        q = __half22float2(u32_as_h2(p0.y)); a2 = fmaf(w0, q.x, a2); a3 = fmaf(w0, q.y, a3);
    }

    const float av[4] = {a0, a1, a2, a3};
    float p0 = 0.f, p1 = 0.f;
#pragma unroll
    for (int jj = 0; jj < 4; jj++) {
        const int k = lane * 4 + jj;
        const float x2 = fmaxf(fmaf(dinv, av[jj], sb1[k]), 0.f);
        p0 = fmaf(x2, sW2[k * 2 + 0], p0);
        p1 = fmaf(x2, sW2[k * 2 + 1], p1);
    }
#pragma unroll
    for (int o = 16; o > 0; o >>= 1) {
        p0 += __shfl_xor_sync(0xffffffffu, p0, o);
        p1 += __shfl_xor_sync(0xffffffffu, p1, o);
    }
    if (lane == 0) ((float2*)g_HS2)[v] = make_float2(dinv * p0, dinv * p1);
}

// ---------------------------------------------------------------------------
// 3) fused layer-2 aggregation + bias
// ---------------------------------------------------------------------------
__global__ __launch_bounds__(256) void gather2_final_kernel(const float* __restrict__ b2,
                                                            float* __restrict__ out) {
    const int v = (blockIdx.x * blockDim.x + threadIdx.x) >> 5;
    const int lane = threadIdx.x & 31;
    if (v >= NN) return;
    const int start = g_rowstart[v];
    const int deg = g_deg[v];
    float2 acc = (lane == 0) ? ((const float2*)g_HS2)[v] : make_float2(0.f, 0.f);
    for (int j = lane; j < deg; j += 32) {
        const float2 h = ((const float2*)g_HS2)[g_csr[start + j]];
        acc.x += h.x; acc.y += h.y;
    }
#pragma unroll
    for (int o = 16; o > 0; o >>= 1) {
        acc.x += __shfl_xor_sync(0xffffffffu, acc.x, o);
        acc.y += __shfl_xor_sync(0xffffffffu, acc.y, o);
    }
    if (lane == 0) {
        const float dinv = g_dinv[v];
        ((float2*)out)[v] = make_float2(fmaf(dinv, acc.x, b2[0]),
                                        fmaf(dinv, acc.y, b2[1]));
    }
}

// ---------------------------------------------------------------------------
extern "C" void kernel_launch(void* const* d_in, const int* in_sizes, int n_in,
                              void* d_out, int out_size) {
    const float* x  = (const float*)d_in[0];
    const int*   ei = (const int*)d_in[1];
    const float* W1 = (const float*)d_in[2];
    const float* b1 = (const float*)d_in[3];
    const float* W2 = (const float*)d_in[4];
    const float* b2 = (const float*)d_in[5];
    float* out = (float*)d_out;

    static cudaStream_t s_side = nullptr;
    static cudaEvent_t ev_fork = nullptr, ev_join = nullptr;
    if (s_side == nullptr) {
        cudaStreamCreateWithFlags(&s_side, cudaStreamNonBlocking);
        cudaEventCreateWithFlags(&ev_fork, cudaEventDisableTiming);
        cudaEventCreateWithFlags(&ev_join, cudaEventDisableTiming);
        cudaFuncSetAttribute(mma_gemm_kernel,
                             cudaFuncAttributeMaxDynamicSharedMemorySize, SM_GEMM_TOT);
    }

    const int T = 256;
    zero_probe_kernel<<<(NN + T - 1) / T, T>>>(ei);
    cudaEventRecord(ev_fork, 0);
    cudaStreamWaitEvent(s_side, ev_fork, 0);

    // side stream: CSR build chain (~46us)
    deg_kernel  <<<(NE + T - 1) / T, T, 0, s_side>>>(ei);
    scan1_kernel<<<NBLK, SCAN_B, 0, s_side>>>();
    scan2_kernel<<<1, 128, 0, s_side>>>();
    scan3_kernel<<<(NN + T - 1) / T, T, 0, s_side>>>();
    fill_kernel <<<(NE + T - 1) / T, T, 0, s_side>>>(ei);
    cudaEventRecord(ev_join, s_side);

    // main stream: W1^T convert + wmma GEMM (hidden under side chain)
    w1t_kernel<<<(D * D + T - 1) / T, T>>>(W1);
    mma_gemm_kernel<<<NTILE, T, SM_GEMM_TOT>>>(x);

    cudaStreamWaitEvent(0, ev_join, 0);
    gather_layer2_kernel<<<(NN * 32 + T - 1) / T, T>>>(b1, W2);
    gather2_final_kernel<<<(NN * 32 + T - 1) / T, T>>>(b2, out);
}